// round 16
// baseline (speedup 1.0000x reference)
#include <cuda_runtime.h>
#include <cuda_bf16.h>
#include <cstdint>
#include <math_constants.h>

#define CDIM 256
#define KCODES 8192
#define NROWS 16384
#define NT 128              // codes per chunk
#define MT 128              // rows per CTA
#define NCHUNKS (KCODES / NT)
#define CAP 256             // candidate slots per row (single-pass headroom)
#define MARGIN 1.0e-3f      // insertion margin
#define RWIN   4.0e-4f      // rescore window (hard bf16-error bound + slack)
#define GTHREADS 256        // 8 warps, warp tile 64x32
#define CLIST 32            // per-row compacted window-set capacity

// ---------------------------------------------------------------------------
// Device globals (allocation-free scratch)
// ---------------------------------------------------------------------------
__device__ __align__(16) __nv_bfloat16 g_Abf[(size_t)NROWS * CDIM];   // [n][c]
__device__ __align__(16) __nv_bfloat16 g_Bbf[(size_t)KCODES * CDIM];  // [k][c]
__device__ float    g_A[NROWS];                          // exact ||x||^2 (strict seq)
__device__ float    g_C[KCODES];                         // exact ||e||^2 (strict seq)
__device__ unsigned g_candk[(size_t)NROWS * CAP];
__device__ float    g_cands[(size_t)NROWS * CAP];
__device__ int      g_cnt[NROWS];
__device__ float    g_thresh[NROWS];
__device__ float    g_partial[NROWS / 32];

// ---------------------------------------------------------------------------
// Helpers
// ---------------------------------------------------------------------------
__device__ __forceinline__ uint32_t smem_to_u32(const void* p) {
    uint32_t a;
    asm("{ .reg .u64 t; cvta.to.shared.u64 t, %1; cvt.u32.u64 %0, t; }" : "=r"(a) : "l"(p));
    return a;
}
__device__ __forceinline__ unsigned f2ord(float f) {
    unsigned u = __float_as_uint(f);
    return (u & 0x80000000u) ? ~u : (u | 0x80000000u);
}
__device__ __forceinline__ float ord2f(unsigned u) {
    return __uint_as_float((u & 0x80000000u) ? (u ^ 0x80000000u) : ~u);
}
__device__ __forceinline__ void ldsm4(uint32_t r[4], uint32_t addr) {
    asm volatile("ldmatrix.sync.aligned.m8n8.x4.shared.b16 {%0,%1,%2,%3}, [%4];"
                 : "=r"(r[0]), "=r"(r[1]), "=r"(r[2]), "=r"(r[3]) : "r"(addr));
}
__device__ __forceinline__ void mma16816(float d[4], const uint32_t a[4],
                                         uint32_t b0, uint32_t b1) {
    asm("mma.sync.aligned.m16n8k16.row.col.f32.bf16.bf16.f32 "
        "{%0,%1,%2,%3}, {%4,%5,%6,%7}, {%8,%9}, {%0,%1,%2,%3};"
        : "+f"(d[0]), "+f"(d[1]), "+f"(d[2]), "+f"(d[3])
        : "r"(a[0]), "r"(a[1]), "r"(a[2]), "r"(a[3]), "r"(b0), "r"(b1));
}
__device__ __forceinline__ void cp16(uint32_t dst, const void* src) {
    asm volatile("cp.async.cg.shared.global [%0], [%1], 16;" :: "r"(dst), "l"(src) : "memory");
}
#define CP_COMMIT() asm volatile("cp.async.commit_group;" ::: "memory")
#define CP_WAIT0()  asm volatile("cp.async.wait_group 0;" ::: "memory")
#define BAR_NAMED(id, cnt) asm volatile("bar.sync %0, %1;" :: "r"(id), "r"(cnt) : "memory")

// ---------------------------------------------------------------------------
// Fused prep: z -> bf16 transposed tile + exact row norms A (strict seq).
// ---------------------------------------------------------------------------
__global__ __launch_bounds__(256)
void conv_az_kernel(const float* __restrict__ z) {
    extern __shared__ float tile[];     // [256][65] floats = 66560 B
    const int tid = threadIdx.x;
    const int n0 = blockIdx.x * 64;
    const int b = n0 >> 10, hw0 = n0 & 1023;
    const int m = tid & 63, c_lo = tid >> 6;

    #pragma unroll 4
    for (int i = 0; i < 64; i++) {
        int c = i * 4 + c_lo;
        tile[c * 65 + m] = z[((size_t)b * CDIM + c) * 1024 + hw0 + m];
    }
    __syncthreads();

    __nv_bfloat162* dst = (__nv_bfloat162*)g_Abf;
    #pragma unroll
    for (int i = 0; i < 32; i++) {
        int u = i * 256 + tid;
        int mm = u >> 7, c2 = u & 127;
        dst[(size_t)(n0 + mm) * 128 + c2] =
            __floats2bfloat162_rn(tile[(2 * c2) * 65 + mm], tile[(2 * c2 + 1) * 65 + mm]);
    }

    if (tid < 64) {
        float s = 0.f;
        #pragma unroll 16
        for (int c = 0; c < CDIM; c++) {
            float v = tile[c * 65 + tid];
            s = __fadd_rn(s, __fmul_rn(v, v));
        }
        g_A[n0 + tid] = s;
    }
}

// ---------------------------------------------------------------------------
// Fused prep: emb -> bf16 + exact code norms C (strict seq).
// ---------------------------------------------------------------------------
__global__ __launch_bounds__(256)
void conv_bc_kernel(const float* __restrict__ emb) {
    extern __shared__ float4 esm[];     // [64][65] float4 = 66560 B
    float* esf = (float*)esm;
    const int tid = threadIdx.x;
    const int k0 = blockIdx.x * 64;
    const float4* src = (const float4*)(emb + (size_t)k0 * CDIM);

    #pragma unroll
    for (int i = 0; i < 16; i++) {
        int g = i * 256 + tid;
        int r = g >> 6, q = g & 63;
        esm[r * 65 + q] = src[g];
    }
    __syncthreads();

    __nv_bfloat162* dst = (__nv_bfloat162*)g_Bbf;
    #pragma unroll
    for (int i = 0; i < 32; i++) {
        int u = i * 256 + tid;
        int r = u >> 7, c2 = u & 127;
        dst[(size_t)(k0 + r) * 128 + c2] =
            __floats2bfloat162_rn(esf[r * 260 + 2 * c2], esf[r * 260 + 2 * c2 + 1]);
    }

    if (tid < 64) {
        float s = 0.f;
        #pragma unroll 8
        for (int q = 0; q < 64; q++) {
            float4 v = esm[tid * 65 + q];
            s = __fadd_rn(s, __fmul_rn(v.x, v.x));
            s = __fadd_rn(s, __fmul_rn(v.y, v.y));
            s = __fadd_rn(s, __fmul_rn(v.z, v.z));
            s = __fadd_rn(s, __fmul_rn(v.w, v.w));
        }
        g_C[k0 + tid] = s;
    }
}

// ---------------------------------------------------------------------------
// GEMM (HMMA mma.sync bf16 f32-acc) + single-pass screening.
// 256 threads, 8 warps in 2(M) x 4(N) grid, warp tile 64x32,
// explicit k-step fragment double-buffering.
// ---------------------------------------------------------------------------
#define SM_A 0
#define SM_B0 65536
#define SM_B1 131072
#define SM_C  196608
#define SM_RMAX (SM_C + 1024)
#define SM_CNT  (SM_RMAX + 512)
#define SM_TOTAL (SM_CNT + 512)

__device__ __forceinline__ void cp_tile(uint32_t dst, const __nv_bfloat16* gsrc, int tid) {
    const char* src = (const char*)gsrc;
    #pragma unroll
    for (int it = 0; it < 16; it++) {
        int u = it * GTHREADS + tid;       // 0..4095 granules of 16B
        int row = u >> 5, gr = u & 31;
        cp16(dst + row * 512 + ((gr ^ (row & 7)) << 4), src + (size_t)u * 16);
    }
}

__global__ __launch_bounds__(GTHREADS, 1)
void gemm_screen_kernel() {
    extern __shared__ char smem[];
    const uint32_t smem_base = smem_to_u32(smem);
    const int tid = threadIdx.x;
    const int wid = tid >> 5, lane = tid & 31;
    const int wm = wid >> 2, wn = wid & 3;       // 2(M) x 4(N) warp grid
    const int g = lane >> 2, tg = lane & 3;
    const int n0 = blockIdx.x * MT;

    float*    C_s     = (float*)(smem + SM_C);
    unsigned* sh_rmax = (unsigned*)(smem + SM_RMAX);
    int*      sh_cnt  = (int*)(smem + SM_CNT);

    if (tid < 128) { sh_rmax[tid] = f2ord(-CUDART_INF_F); sh_cnt[tid] = 0; }

    cp_tile(smem_base + SM_A, g_Abf + (size_t)n0 * CDIM, tid);
    cp_tile(smem_base + SM_B0, g_Bbf, tid);
    CP_COMMIT();
    if (tid < 128) C_s[tid] = g_C[tid];
    CP_WAIT0();
    __syncthreads();

    const uint32_t As_base = smem_base + SM_A;
    // Per-warp fragment addresses (ks-dependent part added in-loop)
    const int arow = wm * 64 + (lane & 15);      // +mt*16
    const int bcol = wn * 32 + ((lane >> 4) << 3) + (lane & 7);   // +bp*16

    for (int i = 0; i < NCHUNKS; i++) {
        const int cur = i & 1, nxt = cur ^ 1;

        if (i + 1 < NCHUNKS) {
            cp_tile(smem_base + (nxt ? SM_B1 : SM_B0),
                    g_Bbf + (size_t)(i + 1) * NT * CDIM, tid);
            CP_COMMIT();
            if (tid < 128) C_s[nxt * 128 + tid] = g_C[(i + 1) * NT + tid];
        }

        // Pre-chunk thresholds (valid for i >= 1)
        float thr[4][2];
        #pragma unroll
        for (int mt = 0; mt < 4; mt++)
            #pragma unroll
            for (int h = 0; h < 2; h++)
                thr[mt][h] = ord2f(sh_rmax[wm * 64 + mt * 16 + h * 8 + g]) - MARGIN;

        // ---- compute chunk i: warp tile 64(M) x 32(N), frag double-buffer ----
        const uint32_t Bs_base = smem_base + (cur ? SM_B1 : SM_B0);
        float acc[4][4][4];
        #pragma unroll
        for (int mt = 0; mt < 4; mt++)
            #pragma unroll
            for (int nt = 0; nt < 4; nt++)
                #pragma unroll
                for (int c = 0; c < 4; c++) acc[mt][nt][c] = 0.f;

        uint32_t a_frag[2][4][4];    // [buf][mt][regs]
        uint32_t b_frag[2][2][4];    // [buf][bp][regs]

        // prologue: load ks=0 fragments
        {
            const int gra = (lane >> 4);
            #pragma unroll
            for (int mt = 0; mt < 4; mt++) {
                int row = arow + mt * 16;
                ldsm4(a_frag[0][mt], As_base + row * 512 + ((gra ^ (row & 7)) << 4));
            }
            const int grb = ((lane >> 3) & 1);
            #pragma unroll
            for (int bp = 0; bp < 2; bp++) {
                int nn = bcol + bp * 16;
                ldsm4(b_frag[0][bp], Bs_base + nn * 512 + ((grb ^ (nn & 7)) << 4));
            }
        }

        #pragma unroll
        for (int ks = 0; ks < 16; ks++) {
            const int cb = ks & 1, nb = cb ^ 1;
            if (ks < 15) {   // prefetch ks+1 fragments before issuing ks MMAs
                const int gra = (ks + 1) * 2 + (lane >> 4);
                #pragma unroll
                for (int mt = 0; mt < 4; mt++) {
                    int row = arow + mt * 16;
                    ldsm4(a_frag[nb][mt], As_base + row * 512 + ((gra ^ (row & 7)) << 4));
                }
                const int grb = (ks + 1) * 2 + ((lane >> 3) & 1);
                #pragma unroll
                for (int bp = 0; bp < 2; bp++) {
                    int nn = bcol + bp * 16;
                    ldsm4(b_frag[nb][bp], Bs_base + nn * 512 + ((grb ^ (nn & 7)) << 4));
                }
            }
            #pragma unroll
            for (int mt = 0; mt < 4; mt++)
                #pragma unroll
                for (int bp = 0; bp < 2; bp++) {
                    mma16816(acc[mt][bp * 2],     a_frag[cb][mt],
                             b_frag[cb][bp][0], b_frag[cb][bp][1]);
                    mma16816(acc[mt][bp * 2 + 1], a_frag[cb][mt],
                             b_frag[cb][bp][2], b_frag[cb][bp][3]);
                }
        }

        // scores in-place + chunk row-max -> sh_rmax
        #pragma unroll
        for (int mt = 0; mt < 4; mt++) {
            float lmax[2] = {-CUDART_INF_F, -CUDART_INF_F};
            #pragma unroll
            for (int nt = 0; nt < 4; nt++)
                #pragma unroll
                for (int h = 0; h < 2; h++)
                    #pragma unroll
                    for (int q = 0; q < 2; q++) {
                        int col = wn * 32 + nt * 8 + tg * 2 + q;
                        float s = __fmaf_rn(2.0f, acc[mt][nt][h * 2 + q],
                                            -C_s[cur * 128 + col]);
                        acc[mt][nt][h * 2 + q] = s;
                        if (s > lmax[h]) lmax[h] = s;
                    }
            #pragma unroll
            for (int h = 0; h < 2; h++) {
                lmax[h] = fmaxf(lmax[h], __shfl_xor_sync(0xffffffffu, lmax[h], 1));
                lmax[h] = fmaxf(lmax[h], __shfl_xor_sync(0xffffffffu, lmax[h], 2));
                if (tg == 0) {
                    int rl = wm * 64 + mt * 16 + h * 8 + g;
                    atomicMax(&sh_rmax[rl], f2ord(lmax[h]));
                }
            }
        }
        if (i == 0) {   // seed chunk: full row-group max, then fresh thresholds
            BAR_NAMED(1 + wm, 128);
            #pragma unroll
            for (int mt = 0; mt < 4; mt++)
                #pragma unroll
                for (int h = 0; h < 2; h++)
                    thr[mt][h] = ord2f(sh_rmax[wm * 64 + mt * 16 + h * 8 + g]) - MARGIN;
        }

        // insert candidates above threshold
        const int k0 = i * NT;
        #pragma unroll
        for (int mt = 0; mt < 4; mt++)
            #pragma unroll
            for (int h = 0; h < 2; h++) {
                int rl = wm * 64 + mt * 16 + h * 8 + g;
                #pragma unroll
                for (int nt = 0; nt < 4; nt++)
                    #pragma unroll
                    for (int q = 0; q < 2; q++) {
                        float s = acc[mt][nt][h * 2 + q];
                        if (s > thr[mt][h]) {
                            int col = wn * 32 + nt * 8 + tg * 2 + q;
                            int slot = atomicAdd(&sh_cnt[rl], 1);
                            if (slot < CAP) {
                                g_candk[(size_t)(n0 + rl) * CAP + slot] = (unsigned)(k0 + col);
                                g_cands[(size_t)(n0 + rl) * CAP + slot] = s;
                            }
                        }
                    }
            }
        if (i + 1 < NCHUNKS) CP_WAIT0();
        __syncthreads();
    }

    if (tid < 128) {
        g_cnt[n0 + tid] = sh_cnt[tid];
        g_thresh[n0 + tid] = ord2f(sh_rmax[tid]) - MARGIN;
    }
}

// ---------------------------------------------------------------------------
// Rescore v5 + fused quantize (R15-validated): 32 rows/block, 8 threads/row.
// ---------------------------------------------------------------------------
__device__ __forceinline__ float exact_d_s(const float* __restrict__ zrow,
                                           const float4* __restrict__ e4,
                                           float A, float C) {
    float P = 0.f;
    #pragma unroll
    for (int c0 = 0; c0 < CDIM; c0 += 16) {
        float4 ev[4];
        #pragma unroll
        for (int u = 0; u < 4; u++) ev[u] = __ldg(e4 + (c0 >> 2) + u);
        #pragma unroll
        for (int u = 0; u < 4; u++) {
            P = __fmaf_rn(zrow[(c0 + 4 * u + 0) * 33], ev[u].x, P);
            P = __fmaf_rn(zrow[(c0 + 4 * u + 1) * 33], ev[u].y, P);
            P = __fmaf_rn(zrow[(c0 + 4 * u + 2) * 33], ev[u].z, P);
            P = __fmaf_rn(zrow[(c0 + 4 * u + 3) * 33], ev[u].w, P);
        }
    }
    float t = __fsub_rn(A, __fmul_rn(2.0f, P));
    return __fadd_rn(t, C);
}

__global__ __launch_bounds__(256)
void rescore_quant_kernel(const float* __restrict__ z, const float* __restrict__ emb,
                          float* __restrict__ out) {
    extern __shared__ float rsm[];
    float* tile  = rsm;                       // [256][33]
    float* s_bd  = rsm + 256 * 33;            // 256 f
    int*   s_bi  = (int*)(s_bd + 256);        // 256 i
    int*   s_cnt = s_bi + 256;                // 32 i
    int*   s_ck  = s_cnt + 32;                // 32*CLIST i
    int*   s_k   = s_ck + 32 * CLIST;         // 32 i

    const int tid = threadIdx.x;
    const int n0 = blockIdx.x * 32;
    const int b = n0 >> 10, hw0 = n0 & 1023;

    {
        const int mm = tid & 31, c_lo = tid >> 5;
        #pragma unroll 4
        for (int i = 0; i < 32; i++) {
            int c = i * 8 + c_lo;
            tile[c * 33 + mm] = z[((size_t)b * CDIM + c) * 1024 + hw0 + mm];
        }
    }
    if (tid < 32) s_cnt[tid] = 0;
    __syncthreads();

    const int m = tid & 31;
    const int part = tid >> 5;
    const int n = n0 + m;
    const float A = g_A[n];
    const int cnt = g_cnt[n];
    const float rcut = (g_thresh[n] + MARGIN) - RWIN;
    const float* zrow = tile + m;

    const bool overflow = (cnt > CAP);
    if (!overflow) {
        for (int l = part; l < cnt; l += 8) {
            if (g_cands[(size_t)n * CAP + l] >= rcut) {
                int p = atomicAdd(&s_cnt[m], 1);
                if (p < CLIST) s_ck[m * CLIST + p] = (int)g_candk[(size_t)n * CAP + l];
            }
        }
    }
    __syncthreads();

    const int rc = s_cnt[m];
    float bd = CUDART_INF_F;
    int bi = 0x7fffffff;
    if (overflow || rc == 0 || rc > CLIST) {
        for (int k = part; k < KCODES; k += 8) {   // safety net
            float d = exact_d_s(zrow, (const float4*)(emb + (size_t)k * CDIM), A, g_C[k]);
            if (d < bd || (d == bd && k < bi)) { bd = d; bi = k; }
        }
    } else if (rc == 1) {
        if (part == 0) { bd = -CUDART_INF_F; bi = s_ck[m * CLIST]; }
    } else {
        for (int l = part; l < rc; l += 8) {
            int k = s_ck[m * CLIST + l];
            float d = exact_d_s(zrow, (const float4*)(emb + (size_t)k * CDIM), A, g_C[k]);
            if (d < bd || (d == bd && k < bi)) { bd = d; bi = k; }
        }
    }
    s_bd[tid] = bd;
    s_bi[tid] = bi;
    __syncthreads();

    if (tid < 32) {
        float fbd = s_bd[tid];
        int   fbi = s_bi[tid];
        #pragma unroll
        for (int j = 1; j < 8; j++) {
            float od = s_bd[tid + j * 32];
            int   oi = s_bi[tid + j * 32];
            if (od < fbd || (od == fbd && oi < fbi)) { fbd = od; fbi = oi; }
        }
        s_k[tid] = fbi;
        out[(size_t)NROWS * CDIM + 2 + n0 + tid] = (float)fbi;
    }
    __syncthreads();

    const float4* erow = (const float4*)emb + (size_t)s_k[m] * 64 + part * 8;
    float* outq = out + (size_t)b * CDIM * 1024 + hw0 + m;
    float lsum = 0.f;
    #pragma unroll
    for (int j = 0; j < 8; j++) {
        float4 ev = __ldg(erow + j);
        int c = part * 32 + j * 4;
        float qv[4] = {ev.x, ev.y, ev.z, ev.w};
        #pragma unroll
        for (int u = 0; u < 4; u++) {
            float zv = zrow[(c + u) * 33];
            float d  = __fsub_rn(qv[u], zv);
            outq[(size_t)(c + u) * 1024] = __fadd_rn(zv, d);
            lsum = __fmaf_rn(d, d, lsum);
        }
    }
    __syncthreads();
    s_bd[tid] = lsum;
    __syncthreads();
    #pragma unroll
    for (int st = 128; st; st >>= 1) {
        if (tid < st) s_bd[tid] += s_bd[tid + st];
        __syncthreads();
    }
    if (tid == 0) g_partial[blockIdx.x] = s_bd[0];
}

__global__ void finalize_kernel(float* __restrict__ out) {
    __shared__ float red[256];
    red[threadIdx.x] = g_partial[threadIdx.x] + g_partial[threadIdx.x + 256];
    __syncthreads();
    #pragma unroll
    for (int st = 128; st; st >>= 1) {
        if (threadIdx.x < st) red[threadIdx.x] += red[threadIdx.x + st];
        __syncthreads();
    }
    if (threadIdx.x == 0) {
        const size_t QELEMS = (size_t)NROWS * CDIM;
        float loss = red[0] / (float)QELEMS;
        out[QELEMS]     = loss;
        out[QELEMS + 1] = 0.25f * loss;
    }
}

// ---------------------------------------------------------------------------
extern "C" void kernel_launch(void* const* d_in, const int* in_sizes, int n_in,
                              void* d_out, int out_size) {
    const float* z   = (const float*)d_in[0];
    const float* emb = (const float*)d_in[1];
    float* out = (float*)d_out;

    constexpr int PREP_SMEM = 66560;
    constexpr int RESC_SMEM = (256 * 33 + 512 + 32 + 32 * CLIST + 32) * 4;
    cudaFuncSetAttribute(gemm_screen_kernel,
                         cudaFuncAttributeMaxDynamicSharedMemorySize, SM_TOTAL);
    cudaFuncSetAttribute(conv_az_kernel,
                         cudaFuncAttributeMaxDynamicSharedMemorySize, PREP_SMEM);
    cudaFuncSetAttribute(conv_bc_kernel,
                         cudaFuncAttributeMaxDynamicSharedMemorySize, PREP_SMEM);
    cudaFuncSetAttribute(rescore_quant_kernel,
                         cudaFuncAttributeMaxDynamicSharedMemorySize, RESC_SMEM);

    conv_az_kernel<<<NROWS / 64, 256, PREP_SMEM>>>(z);
    conv_bc_kernel<<<KCODES / 64, 256, PREP_SMEM>>>(emb);
    gemm_screen_kernel<<<NROWS / MT, GTHREADS, SM_TOTAL>>>();
    rescore_quant_kernel<<<NROWS / 32, 256, RESC_SMEM>>>(z, emb, out);
    finalize_kernel<<<1, 256>>>(out);
}

// round 17
// speedup vs baseline: 1.1599x; 1.1599x over previous
#include <cuda_runtime.h>
#include <cuda_bf16.h>
#include <cstdint>
#include <math_constants.h>

#define CDIM 256
#define KCODES 8192
#define NROWS 16384
#define NT 128              // codes per chunk
#define MT 128              // rows per CTA
#define NCHUNKS (KCODES / NT)
#define CAP 256             // candidate slots per row (single-pass headroom)
#define MARGIN 1.0e-3f      // insertion margin
#define RWIN   4.0e-4f      // rescore window (hard bf16-error bound + slack)
#define GTHREADS 512
#define CLIST 32            // per-row compacted window-set capacity

// ---------------------------------------------------------------------------
// Device globals (allocation-free scratch)
// ---------------------------------------------------------------------------
__device__ __align__(16) __nv_bfloat16 g_Bbf[(size_t)KCODES * CDIM];  // [k][c]
__device__ float    g_A[NROWS];                          // exact ||x||^2 (strict seq)
__device__ float    g_C[KCODES];                         // exact ||e||^2 (strict seq)
__device__ unsigned g_candk[(size_t)NROWS * CAP];
__device__ float    g_cands[(size_t)NROWS * CAP];
__device__ int      g_cnt[NROWS];
__device__ float    g_thresh[NROWS];
__device__ float    g_partial[NROWS / 32];

// ---------------------------------------------------------------------------
// Helpers
// ---------------------------------------------------------------------------
__device__ __forceinline__ uint32_t smem_to_u32(const void* p) {
    uint32_t a;
    asm("{ .reg .u64 t; cvta.to.shared.u64 t, %1; cvt.u32.u64 %0, t; }" : "=r"(a) : "l"(p));
    return a;
}
__device__ __forceinline__ unsigned f2ord(float f) {
    unsigned u = __float_as_uint(f);
    return (u & 0x80000000u) ? ~u : (u | 0x80000000u);
}
__device__ __forceinline__ float ord2f(unsigned u) {
    return __uint_as_float((u & 0x80000000u) ? (u ^ 0x80000000u) : ~u);
}
__device__ __forceinline__ void ldsm4(uint32_t r[4], uint32_t addr) {
    asm volatile("ldmatrix.sync.aligned.m8n8.x4.shared.b16 {%0,%1,%2,%3}, [%4];"
                 : "=r"(r[0]), "=r"(r[1]), "=r"(r[2]), "=r"(r[3]) : "r"(addr));
}
__device__ __forceinline__ void mma16816(float d[4], const uint32_t a[4],
                                         uint32_t b0, uint32_t b1) {
    asm("mma.sync.aligned.m16n8k16.row.col.f32.bf16.bf16.f32 "
        "{%0,%1,%2,%3}, {%4,%5,%6,%7}, {%8,%9}, {%0,%1,%2,%3};"
        : "+f"(d[0]), "+f"(d[1]), "+f"(d[2]), "+f"(d[3])
        : "r"(a[0]), "r"(a[1]), "r"(a[2]), "r"(a[3]), "r"(b0), "r"(b1));
}
__device__ __forceinline__ void cp16(uint32_t dst, const void* src) {
    asm volatile("cp.async.cg.shared.global [%0], [%1], 16;" :: "r"(dst), "l"(src) : "memory");
}
#define CP_COMMIT() asm volatile("cp.async.commit_group;" ::: "memory")
#define CP_WAIT0()  asm volatile("cp.async.wait_group 0;" ::: "memory")
#define BAR_NAMED(id, cnt) asm volatile("bar.sync %0, %1;" :: "r"(id), "r"(cnt) : "memory")

// ---------------------------------------------------------------------------
// Fused prep: emb -> bf16 + exact code norms C (strict seq).
// ---------------------------------------------------------------------------
__global__ __launch_bounds__(256)
void conv_bc_kernel(const float* __restrict__ emb) {
    extern __shared__ float4 esm[];     // [64][65] float4 = 66560 B
    float* esf = (float*)esm;
    const int tid = threadIdx.x;
    const int k0 = blockIdx.x * 64;
    const float4* src = (const float4*)(emb + (size_t)k0 * CDIM);

    #pragma unroll
    for (int i = 0; i < 16; i++) {
        int g = i * 256 + tid;
        int r = g >> 6, q = g & 63;
        esm[r * 65 + q] = src[g];
    }
    __syncthreads();

    __nv_bfloat162* dst = (__nv_bfloat162*)g_Bbf;
    #pragma unroll
    for (int i = 0; i < 32; i++) {
        int u = i * 256 + tid;
        int r = u >> 7, c2 = u & 127;
        dst[(size_t)(k0 + r) * 128 + c2] =
            __floats2bfloat162_rn(esf[r * 260 + 2 * c2], esf[r * 260 + 2 * c2 + 1]);
    }

    if (tid < 64) {
        float s = 0.f;
        #pragma unroll 8
        for (int q = 0; q < 64; q++) {
            float4 v = esm[tid * 65 + q];
            s = __fadd_rn(s, __fmul_rn(v.x, v.x));
            s = __fadd_rn(s, __fmul_rn(v.y, v.y));
            s = __fadd_rn(s, __fmul_rn(v.z, v.z));
            s = __fadd_rn(s, __fmul_rn(v.w, v.w));
        }
        g_C[k0 + tid] = s;
    }
}

// ---------------------------------------------------------------------------
// GEMM (HMMA mma.sync bf16 f32-acc) + single-pass screening (R15-validated
// shape: 512 threads, 16 warps 4x4, warp tile 32x32) + fused A-prep:
// the prologue converts z -> bf16 swizzled A tile in smem directly and
// computes exact strict-sequential row norms (replaces conv_az kernel).
// ---------------------------------------------------------------------------
#define SM_A 0
#define SM_B0 65536
#define SM_B1 131072
#define SM_C  196608
#define SM_RMAX (SM_C + 1024)
#define SM_CNT  (SM_RMAX + 512)
#define SM_TOTAL (SM_CNT + 512)

__device__ __forceinline__ void cp_tile(uint32_t dst, const __nv_bfloat16* gsrc, int tid) {
    const char* src = (const char*)gsrc;
    #pragma unroll
    for (int it = 0; it < 8; it++) {
        int u = it * GTHREADS + tid;
        int row = u >> 5, gr = u & 31;
        cp16(dst + row * 512 + ((gr ^ (row & 7)) << 4), src + (size_t)u * 16);
    }
}

__global__ __launch_bounds__(GTHREADS, 1)
void gemm_screen_kernel(const float* __restrict__ z) {
    extern __shared__ char smem[];
    const uint32_t smem_base = smem_to_u32(smem);
    const int tid = threadIdx.x;
    const int wid = tid >> 5, lane = tid & 31;
    const int wm = wid & 3, wn = wid >> 2;
    const int g = lane >> 2, tg = lane & 3;
    const int n0 = blockIdx.x * MT;

    float*    C_s     = (float*)(smem + SM_C);
    unsigned* sh_rmax = (unsigned*)(smem + SM_RMAX);
    int*      sh_cnt  = (int*)(smem + SM_CNT);

    if (tid < 128) { sh_rmax[tid] = f2ord(-CUDART_INF_F); sh_cnt[tid] = 0; }

    // B chunk 0 async first (overlaps the A conversion below)
    cp_tile(smem_base + SM_B0, g_Bbf, tid);
    CP_COMMIT();
    if (tid < 128) C_s[tid] = g_C[tid];

    // ---- Fused A-prep: z -> bf16 swizzled tile + exact row norms ----
    {
        const int row = tid & 127;       // local row (lanes = consecutive rows)
        const int grp = tid >> 7;        // 0..3
        const float* zc = z + (size_t)(n0 >> 10) * CDIM * 1024 + (n0 & 1023) + row;
        #pragma unroll
        for (int it = 0; it < 8; it++) {
            int gr = grp + it * 4;       // granule 0..31 (8 c-values each)
            float v[8];
            #pragma unroll
            for (int u = 0; u < 8; u++) v[u] = __ldg(zc + (size_t)(gr * 8 + u) * 1024);
            uint32_t p[4];
            #pragma unroll
            for (int u = 0; u < 4; u++) {
                __nv_bfloat162 h = __floats2bfloat162_rn(v[2 * u], v[2 * u + 1]);
                p[u] = *(uint32_t*)&h;
            }
            *(uint4*)(smem + SM_A + row * 512 + ((gr ^ (row & 7)) << 4)) =
                make_uint4(p[0], p[1], p[2], p[3]);
        }
        // Exact A norms: strict sequential fp32 ascending c (L1-warm reloads)
        if (tid < 128) {
            float s = 0.f;
            for (int c0 = 0; c0 < CDIM; c0 += 8) {
                float v[8];
                #pragma unroll
                for (int u = 0; u < 8; u++) v[u] = __ldg(zc + (size_t)(c0 + u) * 1024);
                #pragma unroll
                for (int u = 0; u < 8; u++) s = __fadd_rn(s, __fmul_rn(v[u], v[u]));
            }
            g_A[n0 + row] = s;
        }
    }
    CP_WAIT0();
    __syncthreads();

    const uint32_t As_base = smem_base + SM_A;

    for (int i = 0; i < NCHUNKS; i++) {
        const int cur = i & 1, nxt = cur ^ 1;

        if (i + 1 < NCHUNKS) {
            cp_tile(smem_base + (nxt ? SM_B1 : SM_B0),
                    g_Bbf + (size_t)(i + 1) * NT * CDIM, tid);
            CP_COMMIT();
            if (tid < 128) C_s[nxt * 128 + tid] = g_C[(i + 1) * NT + tid];
        }

        // Pre-chunk thresholds (valid for i >= 1)
        float thr[2][2];
        #pragma unroll
        for (int mt = 0; mt < 2; mt++)
            #pragma unroll
            for (int h = 0; h < 2; h++)
                thr[mt][h] = ord2f(sh_rmax[wm * 32 + mt * 16 + h * 8 + g]) - MARGIN;

        // ---- compute chunk i: warp tile 32(M) x 32(N) ----
        const uint32_t Bs_base = smem_base + (cur ? SM_B1 : SM_B0);
        float acc[2][4][4];
        #pragma unroll
        for (int mt = 0; mt < 2; mt++)
            #pragma unroll
            for (int nt = 0; nt < 4; nt++)
                #pragma unroll
                for (int c = 0; c < 4; c++) acc[mt][nt][c] = 0.f;

        #pragma unroll
        for (int ks = 0; ks < 16; ks++) {
            uint32_t a_frag[2][4];
            #pragma unroll
            for (int mt = 0; mt < 2; mt++) {
                int row = wm * 32 + mt * 16 + (lane & 15);
                int gr  = ks * 2 + (lane >> 4);
                ldsm4(a_frag[mt], As_base + row * 512 + ((gr ^ (row & 7)) << 4));
            }
            uint32_t b_frag[2][4];
            #pragma unroll
            for (int bp = 0; bp < 2; bp++) {
                int n  = wn * 32 + bp * 16 + ((lane >> 4) << 3) + (lane & 7);
                int gr = ks * 2 + ((lane >> 3) & 1);
                ldsm4(b_frag[bp], Bs_base + n * 512 + ((gr ^ (n & 7)) << 4));
            }
            #pragma unroll
            for (int mt = 0; mt < 2; mt++)
                #pragma unroll
                for (int bp = 0; bp < 2; bp++) {
                    mma16816(acc[mt][bp * 2],     a_frag[mt], b_frag[bp][0], b_frag[bp][1]);
                    mma16816(acc[mt][bp * 2 + 1], a_frag[mt], b_frag[bp][2], b_frag[bp][3]);
                }
        }

        // scores in-place + chunk row-max -> sh_rmax
        #pragma unroll
        for (int mt = 0; mt < 2; mt++) {
            float lmax[2] = {-CUDART_INF_F, -CUDART_INF_F};
            #pragma unroll
            for (int nt = 0; nt < 4; nt++)
                #pragma unroll
                for (int h = 0; h < 2; h++)
                    #pragma unroll
                    for (int q = 0; q < 2; q++) {
                        int col = wn * 32 + nt * 8 + tg * 2 + q;
                        float s = __fmaf_rn(2.0f, acc[mt][nt][h * 2 + q],
                                            -C_s[cur * 128 + col]);
                        acc[mt][nt][h * 2 + q] = s;
                        if (s > lmax[h]) lmax[h] = s;
                    }
            #pragma unroll
            for (int h = 0; h < 2; h++) {
                lmax[h] = fmaxf(lmax[h], __shfl_xor_sync(0xffffffffu, lmax[h], 1));
                lmax[h] = fmaxf(lmax[h], __shfl_xor_sync(0xffffffffu, lmax[h], 2));
                if (tg == 0) {
                    int rl = wm * 32 + mt * 16 + h * 8 + g;
                    atomicMax(&sh_rmax[rl], f2ord(lmax[h]));
                }
            }
        }
        if (i == 0) {   // seed chunk: full row-group max, then fresh thresholds
            BAR_NAMED(1 + wm, 128);
            #pragma unroll
            for (int mt = 0; mt < 2; mt++)
                #pragma unroll
                for (int h = 0; h < 2; h++)
                    thr[mt][h] = ord2f(sh_rmax[wm * 32 + mt * 16 + h * 8 + g]) - MARGIN;
        }

        // insert candidates above threshold
        const int k0 = i * NT;
        #pragma unroll
        for (int mt = 0; mt < 2; mt++)
            #pragma unroll
            for (int h = 0; h < 2; h++) {
                int rl = wm * 32 + mt * 16 + h * 8 + g;
                #pragma unroll
                for (int nt = 0; nt < 4; nt++)
                    #pragma unroll
                    for (int q = 0; q < 2; q++) {
                        float s = acc[mt][nt][h * 2 + q];
                        if (s > thr[mt][h]) {
                            int col = wn * 32 + nt * 8 + tg * 2 + q;
                            int slot = atomicAdd(&sh_cnt[rl], 1);
                            if (slot < CAP) {
                                g_candk[(size_t)(n0 + rl) * CAP + slot] = (unsigned)(k0 + col);
                                g_cands[(size_t)(n0 + rl) * CAP + slot] = s;
                            }
                        }
                    }
            }
        if (i + 1 < NCHUNKS) CP_WAIT0();
        __syncthreads();
    }

    if (tid < 128) {
        g_cnt[n0 + tid] = sh_cnt[tid];
        g_thresh[n0 + tid] = ord2f(sh_rmax[tid]) - MARGIN;
    }
}

// ---------------------------------------------------------------------------
// Rescore v5 + fused quantize (R15-validated): 32 rows/block, 8 threads/row.
// ---------------------------------------------------------------------------
__device__ __forceinline__ float exact_d_s(const float* __restrict__ zrow,
                                           const float4* __restrict__ e4,
                                           float A, float C) {
    float P = 0.f;
    #pragma unroll
    for (int c0 = 0; c0 < CDIM; c0 += 16) {
        float4 ev[4];
        #pragma unroll
        for (int u = 0; u < 4; u++) ev[u] = __ldg(e4 + (c0 >> 2) + u);
        #pragma unroll
        for (int u = 0; u < 4; u++) {
            P = __fmaf_rn(zrow[(c0 + 4 * u + 0) * 33], ev[u].x, P);
            P = __fmaf_rn(zrow[(c0 + 4 * u + 1) * 33], ev[u].y, P);
            P = __fmaf_rn(zrow[(c0 + 4 * u + 2) * 33], ev[u].z, P);
            P = __fmaf_rn(zrow[(c0 + 4 * u + 3) * 33], ev[u].w, P);
        }
    }
    float t = __fsub_rn(A, __fmul_rn(2.0f, P));
    return __fadd_rn(t, C);
}

__global__ __launch_bounds__(256)
void rescore_quant_kernel(const float* __restrict__ z, const float* __restrict__ emb,
                          float* __restrict__ out) {
    extern __shared__ float rsm[];
    float* tile  = rsm;                       // [256][33]
    float* s_bd  = rsm + 256 * 33;            // 256 f
    int*   s_bi  = (int*)(s_bd + 256);        // 256 i
    int*   s_cnt = s_bi + 256;                // 32 i
    int*   s_ck  = s_cnt + 32;                // 32*CLIST i
    int*   s_k   = s_ck + 32 * CLIST;         // 32 i

    const int tid = threadIdx.x;
    const int n0 = blockIdx.x * 32;
    const int b = n0 >> 10, hw0 = n0 & 1023;

    {
        const int mm = tid & 31, c_lo = tid >> 5;
        #pragma unroll 4
        for (int i = 0; i < 32; i++) {
            int c = i * 8 + c_lo;
            tile[c * 33 + mm] = z[((size_t)b * CDIM + c) * 1024 + hw0 + mm];
        }
    }
    if (tid < 32) s_cnt[tid] = 0;
    __syncthreads();

    const int m = tid & 31;
    const int part = tid >> 5;
    const int n = n0 + m;
    const float A = g_A[n];
    const int cnt = g_cnt[n];
    const float rcut = (g_thresh[n] + MARGIN) - RWIN;
    const float* zrow = tile + m;

    const bool overflow = (cnt > CAP);
    if (!overflow) {
        for (int l = part; l < cnt; l += 8) {
            if (g_cands[(size_t)n * CAP + l] >= rcut) {
                int p = atomicAdd(&s_cnt[m], 1);
                if (p < CLIST) s_ck[m * CLIST + p] = (int)g_candk[(size_t)n * CAP + l];
            }
        }
    }
    __syncthreads();

    const int rc = s_cnt[m];
    float bd = CUDART_INF_F;
    int bi = 0x7fffffff;
    if (overflow || rc == 0 || rc > CLIST) {
        for (int k = part; k < KCODES; k += 8) {   // safety net
            float d = exact_d_s(zrow, (const float4*)(emb + (size_t)k * CDIM), A, g_C[k]);
            if (d < bd || (d == bd && k < bi)) { bd = d; bi = k; }
        }
    } else if (rc == 1) {
        if (part == 0) { bd = -CUDART_INF_F; bi = s_ck[m * CLIST]; }
    } else {
        for (int l = part; l < rc; l += 8) {
            int k = s_ck[m * CLIST + l];
            float d = exact_d_s(zrow, (const float4*)(emb + (size_t)k * CDIM), A, g_C[k]);
            if (d < bd || (d == bd && k < bi)) { bd = d; bi = k; }
        }
    }
    s_bd[tid] = bd;
    s_bi[tid] = bi;
    __syncthreads();

    if (tid < 32) {
        float fbd = s_bd[tid];
        int   fbi = s_bi[tid];
        #pragma unroll
        for (int j = 1; j < 8; j++) {
            float od = s_bd[tid + j * 32];
            int   oi = s_bi[tid + j * 32];
            if (od < fbd || (od == fbd && oi < fbi)) { fbd = od; fbi = oi; }
        }
        s_k[tid] = fbi;
        out[(size_t)NROWS * CDIM + 2 + n0 + tid] = (float)fbi;
    }
    __syncthreads();

    const float4* erow = (const float4*)emb + (size_t)s_k[m] * 64 + part * 8;
    float* outq = out + (size_t)b * CDIM * 1024 + hw0 + m;
    float lsum = 0.f;
    #pragma unroll
    for (int j = 0; j < 8; j++) {
        float4 ev = __ldg(erow + j);
        int c = part * 32 + j * 4;
        float qv[4] = {ev.x, ev.y, ev.z, ev.w};
        #pragma unroll
        for (int u = 0; u < 4; u++) {
            float zv = zrow[(c + u) * 33];
            float d  = __fsub_rn(qv[u], zv);
            outq[(size_t)(c + u) * 1024] = __fadd_rn(zv, d);
            lsum = __fmaf_rn(d, d, lsum);
        }
    }
    __syncthreads();
    s_bd[tid] = lsum;
    __syncthreads();
    #pragma unroll
    for (int st = 128; st; st >>= 1) {
        if (tid < st) s_bd[tid] += s_bd[tid + st];
        __syncthreads();
    }
    if (tid == 0) g_partial[blockIdx.x] = s_bd[0];
}

__global__ void finalize_kernel(float* __restrict__ out) {
    __shared__ float red[256];
    red[threadIdx.x] = g_partial[threadIdx.x] + g_partial[threadIdx.x + 256];
    __syncthreads();
    #pragma unroll
    for (int st = 128; st; st >>= 1) {
        if (threadIdx.x < st) red[threadIdx.x] += red[threadIdx.x + st];
        __syncthreads();
    }
    if (threadIdx.x == 0) {
        const size_t QELEMS = (size_t)NROWS * CDIM;
        float loss = red[0] / (float)QELEMS;
        out[QELEMS]     = loss;
        out[QELEMS + 1] = 0.25f * loss;
    }
}

// ---------------------------------------------------------------------------
extern "C" void kernel_launch(void* const* d_in, const int* in_sizes, int n_in,
                              void* d_out, int out_size) {
    const float* z   = (const float*)d_in[0];
    const float* emb = (const float*)d_in[1];
    float* out = (float*)d_out;

    constexpr int PREP_SMEM = 66560;
    constexpr int RESC_SMEM = (256 * 33 + 512 + 32 + 32 * CLIST + 32) * 4;
    cudaFuncSetAttribute(gemm_screen_kernel,
                         cudaFuncAttributeMaxDynamicSharedMemorySize, SM_TOTAL);
    cudaFuncSetAttribute(conv_bc_kernel,
                         cudaFuncAttributeMaxDynamicSharedMemorySize, PREP_SMEM);
    cudaFuncSetAttribute(rescore_quant_kernel,
                         cudaFuncAttributeMaxDynamicSharedMemorySize, RESC_SMEM);

    conv_bc_kernel<<<KCODES / 64, 256, PREP_SMEM>>>(emb);
    gemm_screen_kernel<<<NROWS / MT, GTHREADS, SM_TOTAL>>>(z);
    rescore_quant_kernel<<<NROWS / 32, 256, RESC_SMEM>>>(z, emb, out);
    finalize_kernel<<<1, 256>>>(out);
}